// round 1
// baseline (speedup 1.0000x reference)
#include <cuda_runtime.h>

#define WD 512
#define BAND 32
#define RB 4
#define NBATCH (BAND / RB)

// [0],[1]: cc sums per channel; [2]: sum dx^2; [3]: sum dy^2
__device__ double g_acc[4];

__global__ void zero_acc_kernel() {
    if (threadIdx.x < 4) g_acc[threadIdx.x] = 0.0;
}

__global__ __launch_bounds__(512, 2) void ncc_kernel(const float* __restrict__ I,
                                                     const float* __restrict__ J) {
    __shared__ __align__(16) float cb[RB][5][520];
    __shared__ float red[16];

    const int t = threadIdx.x;
    const int blk = blockIdx.x;
    const int img = blk >> 4;      // 16 bands per image, 32 images
    const int band = blk & 15;
    const int r0 = band * BAND;
    const size_t base = (size_t)img * (WD * WD);
    const float* __restrict__ Ip = I + base;
    const float* __restrict__ Jp = J + base;

    // zero the horizontal padding (cols 0..3 and 516..519), written once
    if (t < 4) {
#pragma unroll
        for (int rr = 0; rr < RB; rr++)
#pragma unroll
            for (int q = 0; q < 5; q++) {
                cb[rr][q][t] = 0.0f;
                cb[rr][q][516 + t] = 0.0f;
            }
    }

    // vertical sliding column sums: invariant at loop top = rows [r-4, r+3]
    float cs0 = 0.f, cs1 = 0.f, cs2 = 0.f, cs3 = 0.f, cs4 = 0.f;
#pragma unroll
    for (int k = 0; k < 8; k++) {
        int rr = r0 - 4 + k;                 // r0+3 <= 483 < 512 always
        if (rr >= 0) {
            float a = Ip[rr * WD + t];
            float b = Jp[rr * WD + t];
            cs0 += a; cs1 += b; cs2 += a * a; cs3 += b * b; cs4 += a * b;
        }
    }
    __syncthreads();   // padding visible before first phase-B

    float acc = 0.f;
    const int rsB = t >> 7;      // which of the 4 staged rows
    const int seg = t & 127;     // 4-column run: cols [seg*4, seg*4+4)
    const float inv81 = 1.0f / 81.0f;

    for (int batch = 0; batch < NBATCH; batch++) {
        const int rbase = r0 + batch * RB;
#pragma unroll
        for (int rr = 0; rr < RB; rr++) {
            const int r = rbase + rr;
            float a = 0.f, b = 0.f;
            if (r + 4 < WD) { a = Ip[(r + 4) * WD + t]; b = Jp[(r + 4) * WD + t]; }
            cs0 += a; cs1 += b; cs2 += a * a; cs3 += b * b; cs4 += a * b;
            cb[rr][0][4 + t] = cs0;
            cb[rr][1][4 + t] = cs1;
            cb[rr][2][4 + t] = cs2;
            cb[rr][3][4 + t] = cs3;
            cb[rr][4][4 + t] = cs4;
            float c = 0.f, d = 0.f;
            if (r - 4 >= 0) { c = Ip[(r - 4) * WD + t]; d = Jp[(r - 4) * WD + t]; }
            cs0 -= c; cs1 -= d; cs2 -= c * c; cs3 -= d * d; cs4 -= c * d;
        }
        __syncthreads();

        // horizontal pass: 9-wide sliding sums over 12-float window (3x LDS.128)
        float S[5][4];
#pragma unroll
        for (int q = 0; q < 5; q++) {
            const float4* row4 = (const float4*)cb[rsB][q];
            float4 A = row4[seg], B = row4[seg + 1], C = row4[seg + 2];
            float s = A.x + A.y + A.z + A.w + B.x + B.y + B.z + B.w + C.x;
            S[q][0] = s;
            s += C.y - A.x; S[q][1] = s;
            s += C.z - A.y; S[q][2] = s;
            s += C.w - A.z; S[q][3] = s;
        }
#pragma unroll
        for (int i = 0; i < 4; i++) {
            float sI = S[0][i], sJ = S[1][i];
            float sII = S[2][i], sJJ = S[3][i], sIJ = S[4][i];
            float cross = sIJ - sI * sJ * inv81;
            float Iv = sII - sI * sI * inv81;
            float Jv = sJJ - sJ * sJ * inv81;
            acc += __fdividef(cross * cross, Iv * Jv + 1e-5f);
        }
        __syncthreads();   // before phase-A overwrites cb
    }

    // block reduction
#pragma unroll
    for (int d = 16; d > 0; d >>= 1) acc += __shfl_down_sync(0xffffffffu, acc, d);
    if ((t & 31) == 0) red[t >> 5] = acc;
    __syncthreads();
    if (t < 32) {
        float v = (t < 16) ? red[t] : 0.f;
#pragma unroll
        for (int d = 8; d > 0; d >>= 1) v += __shfl_down_sync(0xffffffffu, v, d);
        if (t == 0) atomicAdd(&g_acc[img & 1], (double)v);
    }
}

__global__ __launch_bounds__(256) void grad_kernel(const float* __restrict__ v, int n) {
    float adx = 0.f, ady = 0.f;
    for (int idx = blockIdx.x * blockDim.x + threadIdx.x; idx < n;
         idx += gridDim.x * blockDim.x) {
        const int hw = idx & 65535;           // position within one 256x256 map
        const float c = v[idx];
        if ((hw & 255) != 255) { float d = v[idx + 1] - c; adx += d * d; }
        if (hw < 65280)        { float d = v[idx + 256] - c; ady += d * d; }
    }
#pragma unroll
    for (int d = 16; d > 0; d >>= 1) {
        adx += __shfl_down_sync(0xffffffffu, adx, d);
        ady += __shfl_down_sync(0xffffffffu, ady, d);
    }
    __shared__ float rx[8], ry[8];
    const int t = threadIdx.x;
    if ((t & 31) == 0) { rx[t >> 5] = adx; ry[t >> 5] = ady; }
    __syncthreads();
    if (t < 32) {
        float x = (t < 8) ? rx[t] : 0.f;
        float y = (t < 8) ? ry[t] : 0.f;
#pragma unroll
        for (int d = 4; d > 0; d >>= 1) {
            x += __shfl_down_sync(0xffffffffu, x, d);
            y += __shfl_down_sync(0xffffffffu, y, d);
        }
        if (t == 0) {
            atomicAdd(&g_acc[2], (double)x);
            atomicAdd(&g_acc[3], (double)y);
        }
    }
}

__global__ void finalize_kernel(float* out) {
    // ncc = -(m0 + m1)/(C-1), C=2; m_c = sum_c / (B*H*W)
    double ncc = -(g_acc[0] + g_acc[1]) / (16.0 * 512.0 * 512.0);
    // grad = 0.01 * ((mean(dx^2)+mean(dy^2))/2 * 2.0)
    double Nd = 16.0 * 2.0 * 256.0 * 255.0;
    double grad = 0.01 * (g_acc[2] / Nd + g_acc[3] / Nd);
    out[0] = (float)(ncc + grad);
    out[1] = (float)ncc;
    out[2] = (float)grad;
}

extern "C" void kernel_launch(void* const* d_in, const int* in_sizes, int n_in,
                              void* d_out, int out_size) {
    const float* y_true = (const float*)d_in[0];
    const float* y_pred = (const float*)d_in[1];
    const float* dvf    = (const float*)d_in[2];
    float* out = (float*)d_out;
    const int n_dvf = in_sizes[2];

    zero_acc_kernel<<<1, 32>>>();
    ncc_kernel<<<32 * 16, 512>>>(y_true, y_pred);
    grad_kernel<<<2048, 256>>>(dvf, n_dvf);
    finalize_kernel<<<1, 1>>>(out);
}

// round 2
// speedup vs baseline: 1.2399x; 1.2399x over previous
#include <cuda_runtime.h>

#define WD 512
#define BAND 32
#define RB 4
#define NBATCH (BAND / RB)

#define NCC_BLOCKS 512
#define GRAD_BLOCKS 64
#define TOTAL_BLOCKS (NCC_BLOCKS + GRAD_BLOCKS)

// [0],[1]: cc sums per channel; [2]: sum dx^2; [3]: sum dy^2
__device__ double g_acc[4];
__device__ unsigned int g_count;

__global__ __launch_bounds__(512, 2) void fused_kernel(const float* __restrict__ I,
                                                       const float* __restrict__ J,
                                                       const float* __restrict__ dvf,
                                                       int n_dvf,
                                                       float* __restrict__ out) {
    __shared__ __align__(16) float cb[RB][5][520];
    __shared__ float red[16];
    __shared__ bool is_last;

    const int t = threadIdx.x;
    const int blk = blockIdx.x;

    if (blk < NCC_BLOCKS) {
        // ───────────────────────── NCC block ─────────────────────────
        const int img = blk >> 4;      // 16 bands per image, 32 images
        const int band = blk & 15;
        const int r0 = band * BAND;
        const size_t base = (size_t)img * (WD * WD);
        const float* __restrict__ Ip = I + base;
        const float* __restrict__ Jp = J + base;

        // zero the horizontal padding (cols 0..3 and 516..519), written once
        if (t < 4) {
#pragma unroll
            for (int rr = 0; rr < RB; rr++)
#pragma unroll
                for (int q = 0; q < 5; q++) {
                    cb[rr][q][t] = 0.0f;
                    cb[rr][q][516 + t] = 0.0f;
                }
        }

        // vertical sliding column sums: invariant at loop top = rows [r-4, r+3]
        float cs0 = 0.f, cs1 = 0.f, cs2 = 0.f, cs3 = 0.f, cs4 = 0.f;
#pragma unroll
        for (int k = 0; k < 8; k++) {
            int rr = r0 - 4 + k;                 // r0+3 <= 483 < 512 always
            if (rr >= 0) {
                float a = Ip[rr * WD + t];
                float b = Jp[rr * WD + t];
                cs0 += a; cs1 += b; cs2 += a * a; cs3 += b * b; cs4 += a * b;
            }
        }
        __syncthreads();   // padding visible before first phase-B

        float acc = 0.f;
        const int rsB = t >> 7;      // which of the 4 staged rows
        const int seg = t & 127;     // 4-column run: cols [seg*4, seg*4+4)
        const float inv81 = 1.0f / 81.0f;

        for (int batch = 0; batch < NBATCH; batch++) {
            const int rbase = r0 + batch * RB;
#pragma unroll
            for (int rr = 0; rr < RB; rr++) {
                const int r = rbase + rr;
                float a = 0.f, b = 0.f;
                if (r + 4 < WD) { a = Ip[(r + 4) * WD + t]; b = Jp[(r + 4) * WD + t]; }
                cs0 += a; cs1 += b; cs2 += a * a; cs3 += b * b; cs4 += a * b;
                cb[rr][0][4 + t] = cs0;
                cb[rr][1][4 + t] = cs1;
                cb[rr][2][4 + t] = cs2;
                cb[rr][3][4 + t] = cs3;
                cb[rr][4][4 + t] = cs4;
                float c = 0.f, d = 0.f;
                if (r - 4 >= 0) { c = Ip[(r - 4) * WD + t]; d = Jp[(r - 4) * WD + t]; }
                cs0 -= c; cs1 -= d; cs2 -= c * c; cs3 -= d * d; cs4 -= c * d;
            }
            __syncthreads();

            // horizontal pass: 9-wide sliding sums over 12-float window (3x LDS.128)
            float S[5][4];
#pragma unroll
            for (int q = 0; q < 5; q++) {
                const float4* row4 = (const float4*)cb[rsB][q];
                float4 A = row4[seg], B = row4[seg + 1], C = row4[seg + 2];
                float s = A.x + A.y + A.z + A.w + B.x + B.y + B.z + B.w + C.x;
                S[q][0] = s;
                s += C.y - A.x; S[q][1] = s;
                s += C.z - A.y; S[q][2] = s;
                s += C.w - A.z; S[q][3] = s;
            }
#pragma unroll
            for (int i = 0; i < 4; i++) {
                float sI = S[0][i], sJ = S[1][i];
                float sII = S[2][i], sJJ = S[3][i], sIJ = S[4][i];
                float cross = sIJ - sI * sJ * inv81;
                float Iv = sII - sI * sI * inv81;
                float Jv = sJJ - sJ * sJ * inv81;
                acc += __fdividef(cross * cross, Iv * Jv + 1e-5f);
            }
            __syncthreads();   // before phase-A overwrites cb
        }

        // block reduction
#pragma unroll
        for (int d = 16; d > 0; d >>= 1) acc += __shfl_down_sync(0xffffffffu, acc, d);
        if ((t & 31) == 0) red[t >> 5] = acc;
        __syncthreads();
        if (t < 32) {
            float v = (t < 16) ? red[t] : 0.f;
#pragma unroll
            for (int d = 8; d > 0; d >>= 1) v += __shfl_down_sync(0xffffffffu, v, d);
            if (t == 0) atomicAdd(&g_acc[img & 1], (double)v);
        }
    } else {
        // ───────────────────────── grad block ─────────────────────────
        float adx = 0.f, ady = 0.f;
        const int gb = blk - NCC_BLOCKS;
        for (int idx = gb * 512 + t; idx < n_dvf; idx += GRAD_BLOCKS * 512) {
            const int hw = idx & 65535;           // position within one 256x256 map
            const float c = dvf[idx];
            if ((hw & 255) != 255) { float d = dvf[idx + 1] - c; adx += d * d; }
            if (hw < 65280)        { float d = dvf[idx + 256] - c; ady += d * d; }
        }
#pragma unroll
        for (int d = 16; d > 0; d >>= 1) {
            adx += __shfl_down_sync(0xffffffffu, adx, d);
            ady += __shfl_down_sync(0xffffffffu, ady, d);
        }
        if ((t & 31) == 0) { red[t >> 5] = adx; cb[0][0][t >> 5] = ady; }
        __syncthreads();
        if (t < 32) {
            float x = (t < 16) ? red[t] : 0.f;
            float y = (t < 16) ? cb[0][0][t] : 0.f;
#pragma unroll
            for (int d = 8; d > 0; d >>= 1) {
                x += __shfl_down_sync(0xffffffffu, x, d);
                y += __shfl_down_sync(0xffffffffu, y, d);
            }
            if (t == 0) {
                atomicAdd(&g_acc[2], (double)x);
                atomicAdd(&g_acc[3], (double)y);
            }
        }
    }

    // ───────────────── last-block finalize (graph-replay safe) ─────────────────
    __threadfence();
    if (t == 0) {
        unsigned int prev = atomicAdd(&g_count, 1u);
        is_last = (prev == (unsigned int)(TOTAL_BLOCKS - 1));
    }
    __syncthreads();
    if (is_last && t == 0) {
        // ncc = -(m0 + m1)/(C-1), C=2; m_c = sum_c / (B*H*W)
        double ncc = -(g_acc[0] + g_acc[1]) / (16.0 * 512.0 * 512.0);
        // grad = 0.01 * ((mean(dx^2)+mean(dy^2))/2 * 2.0)
        double Nd = 16.0 * 2.0 * 256.0 * 255.0;
        double grad = 0.01 * (g_acc[2] / Nd + g_acc[3] / Nd);
        out[0] = (float)(ncc + grad);
        out[1] = (float)ncc;
        out[2] = (float)grad;
        g_acc[0] = 0.0; g_acc[1] = 0.0; g_acc[2] = 0.0; g_acc[3] = 0.0;
        g_count = 0u;
    }
}

extern "C" void kernel_launch(void* const* d_in, const int* in_sizes, int n_in,
                              void* d_out, int out_size) {
    const float* y_true = (const float*)d_in[0];
    const float* y_pred = (const float*)d_in[1];
    const float* dvf    = (const float*)d_in[2];
    float* out = (float*)d_out;
    const int n_dvf = in_sizes[2];

    fused_kernel<<<TOTAL_BLOCKS, 512>>>(y_true, y_pred, dvf, n_dvf, out);
}

// round 3
// speedup vs baseline: 1.3470x; 1.0864x over previous
#include <cuda_runtime.h>

#define WD 512
#define BAND 32
#define RB 4
#define NBATCH (BAND / RB)
#define ROWF 520            // 4 pad + 512 + 4 pad
#define NCC_BLOCKS 512
#define GRAD_BLOCKS 64
#define TOTAL_BLOCKS (NCC_BLOCKS + GRAD_BLOCKS)
#define SMEM_BYTES (2 * RB * 5 * ROWF * 4)   // 83200 B, double-buffered

// [0],[1]: cc sums per channel; [2]: sum dx^2; [3]: sum dy^2
__device__ double g_acc[4];
__device__ unsigned int g_count;

__global__ __launch_bounds__(512, 2) void fused_kernel(const float* __restrict__ I,
                                                       const float* __restrict__ J,
                                                       const float* __restrict__ dvf,
                                                       int n_dvf,
                                                       float* __restrict__ out) {
    extern __shared__ __align__(16) float dyn[];   // [2][RB][5][ROWF]
    __shared__ float red[16];
    __shared__ float red2[16];
    __shared__ bool is_last;

    const int t = threadIdx.x;
    const int blk = blockIdx.x;

    if (blk < NCC_BLOCKS) {
        // ───────────────────────── NCC block ─────────────────────────
        const int img = blk >> 4;      // 16 bands per image, 32 images
        const int band = blk & 15;
        const int r0 = band * BAND;
        const size_t base = (size_t)img * (WD * WD);
        const float* __restrict__ Ip = I + base;
        const float* __restrict__ Jp = J + base;

        // zero the horizontal padding (cols 0..3 and 516..519) in BOTH buffers
        if (t < 4) {
#pragma unroll
            for (int bu = 0; bu < 2; bu++)
#pragma unroll
                for (int rr = 0; rr < RB; rr++)
#pragma unroll
                    for (int q = 0; q < 5; q++) {
                        float* row = dyn + (size_t)(((bu * RB) + rr) * 5 + q) * ROWF;
                        row[t] = 0.0f;
                        row[516 + t] = 0.0f;
                    }
        }

        // vertical sliding column sums: invariant at loop top = rows [r-4, r+3]
        float cs0 = 0.f, cs1 = 0.f, cs2 = 0.f, cs3 = 0.f, cs4 = 0.f;
#pragma unroll
        for (int k = 0; k < 8; k++) {
            int rr = r0 - 4 + k;
            if (rr >= 0) {
                float a = Ip[rr * WD + t];
                float b = Jp[rr * WD + t];
                cs0 += a; cs1 += b; cs2 += a * a; cs3 += b * b; cs4 += a * b;
            }
        }

        // phase A: stage RB rows of column sums into buffer `buf`
        auto phaseA = [&](int buf, int rbase) {
#pragma unroll
            for (int rr = 0; rr < RB; rr++) {
                const int r = rbase + rr;
                float a = 0.f, b = 0.f;
                if (r + 4 < WD) { a = Ip[(r + 4) * WD + t]; b = Jp[(r + 4) * WD + t]; }
                cs0 += a; cs1 += b; cs2 += a * a; cs3 += b * b; cs4 += a * b;
                float* rowp = dyn + (size_t)((buf * RB + rr) * 5) * ROWF + 4 + t;
                rowp[0 * ROWF] = cs0;
                rowp[1 * ROWF] = cs1;
                rowp[2 * ROWF] = cs2;
                rowp[3 * ROWF] = cs3;
                rowp[4 * ROWF] = cs4;
                float c = 0.f, d = 0.f;
                if (r - 4 >= 0) { c = Ip[(r - 4) * WD + t]; d = Jp[(r - 4) * WD + t]; }
                cs0 -= c; cs1 -= d; cs2 -= c * c; cs3 -= d * d; cs4 -= c * d;
            }
        };

        float acc = 0.f;
        const int rsB = t >> 7;      // which of the 4 staged rows
        const int seg = t & 127;     // 4-column run: cols [seg*4, seg*4+4)
        const float inv81 = 1.0f / 81.0f;

        // phase B: horizontal 9-sums + cc for buffer `buf`
        auto phaseB = [&](int buf) {
            float S[5][4];
#pragma unroll
            for (int q = 0; q < 5; q++) {
                const float4* row4 =
                    (const float4*)(dyn + (size_t)((buf * RB + rsB) * 5 + q) * ROWF);
                float4 A = row4[seg], B = row4[seg + 1], C = row4[seg + 2];
                float s = A.x + A.y + A.z + A.w + B.x + B.y + B.z + B.w + C.x;
                S[q][0] = s;
                s += C.y - A.x; S[q][1] = s;
                s += C.z - A.y; S[q][2] = s;
                s += C.w - A.z; S[q][3] = s;
            }
#pragma unroll
            for (int i = 0; i < 4; i++) {
                float sI = S[0][i], sJ = S[1][i];
                float sII = S[2][i], sJJ = S[3][i], sIJ = S[4][i];
                float cross = sIJ - sI * sJ * inv81;
                float Iv = sII - sI * sI * inv81;
                float Jv = sJJ - sJ * sJ * inv81;
                acc += __fdividef(cross * cross, Iv * Jv + 1e-5f);
            }
        };

        __syncthreads();              // padding visible
        phaseA(0, r0);
        __syncthreads();              // buf0 ready

        for (int b = 0; b < NBATCH; b++) {
            if (b + 1 < NBATCH) phaseA((b + 1) & 1, r0 + (b + 1) * RB);  // overlaps B(b)
            phaseB(b & 1);
            __syncthreads();          // protects buf reuse at A(b+2) / publishes A(b+1)
        }

        // block reduction
#pragma unroll
        for (int d = 16; d > 0; d >>= 1) acc += __shfl_down_sync(0xffffffffu, acc, d);
        if ((t & 31) == 0) red[t >> 5] = acc;
        __syncthreads();
        if (t < 32) {
            float v = (t < 16) ? red[t] : 0.f;
#pragma unroll
            for (int d = 8; d > 0; d >>= 1) v += __shfl_down_sync(0xffffffffu, v, d);
            if (t == 0) atomicAdd(&g_acc[img & 1], (double)v);
        }
    } else {
        // ───────────────────────── grad block ─────────────────────────
        float adx = 0.f, ady = 0.f;
        const int gb = blk - NCC_BLOCKS;
        for (int idx = gb * 512 + t; idx < n_dvf; idx += GRAD_BLOCKS * 512) {
            const int hw = idx & 65535;           // position within one 256x256 map
            const float c = dvf[idx];
            if ((hw & 255) != 255) { float d = dvf[idx + 1] - c; adx += d * d; }
            if (hw < 65280)        { float d = dvf[idx + 256] - c; ady += d * d; }
        }
#pragma unroll
        for (int d = 16; d > 0; d >>= 1) {
            adx += __shfl_down_sync(0xffffffffu, adx, d);
            ady += __shfl_down_sync(0xffffffffu, ady, d);
        }
        if ((t & 31) == 0) { red[t >> 5] = adx; red2[t >> 5] = ady; }
        __syncthreads();
        if (t < 32) {
            float x = (t < 16) ? red[t] : 0.f;
            float y = (t < 16) ? red2[t] : 0.f;
#pragma unroll
            for (int d = 8; d > 0; d >>= 1) {
                x += __shfl_down_sync(0xffffffffu, x, d);
                y += __shfl_down_sync(0xffffffffu, y, d);
            }
            if (t == 0) {
                atomicAdd(&g_acc[2], (double)x);
                atomicAdd(&g_acc[3], (double)y);
            }
        }
    }

    // ───────────────── last-block finalize (graph-replay safe) ─────────────────
    __threadfence();
    if (t == 0) {
        unsigned int prev = atomicAdd(&g_count, 1u);
        is_last = (prev == (unsigned int)(TOTAL_BLOCKS - 1));
    }
    __syncthreads();
    if (is_last && t == 0) {
        // ncc = -(m0 + m1)/(C-1), C=2; m_c = sum_c / (B*H*W)
        double ncc = -(g_acc[0] + g_acc[1]) / (16.0 * 512.0 * 512.0);
        // grad = 0.01 * ((mean(dx^2)+mean(dy^2))/2 * 2.0)
        double Nd = 16.0 * 2.0 * 256.0 * 255.0;
        double grad = 0.01 * (g_acc[2] / Nd + g_acc[3] / Nd);
        out[0] = (float)(ncc + grad);
        out[1] = (float)ncc;
        out[2] = (float)grad;
        g_acc[0] = 0.0; g_acc[1] = 0.0; g_acc[2] = 0.0; g_acc[3] = 0.0;
        g_count = 0u;
    }
}

extern "C" void kernel_launch(void* const* d_in, const int* in_sizes, int n_in,
                              void* d_out, int out_size) {
    const float* y_true = (const float*)d_in[0];
    const float* y_pred = (const float*)d_in[1];
    const float* dvf    = (const float*)d_in[2];
    float* out = (float*)d_out;
    const int n_dvf = in_sizes[2];

    cudaFuncSetAttribute(fused_kernel, cudaFuncAttributeMaxDynamicSharedMemorySize,
                         SMEM_BYTES);
    fused_kernel<<<TOTAL_BLOCKS, 512, SMEM_BYTES>>>(y_true, y_pred, dvf, n_dvf, out);
}